// round 11
// baseline (speedup 1.0000x reference)
#include <cuda_runtime.h>
#include <cuda_bf16.h>

typedef unsigned long long u64;

#define NOBJ 7
#define MAXB 50000
#define TWO_PI 6.283185307179586f
#define LN_SIGMA 3.2188758248682006f   /* ln(25) */

/* precomputed sigma contributions: Y[b][4][64] =
   { xs_b@W2S_sig + b2a, xs_b@W2N_sig, xs_b@W3S_sig + b3a, xs_b@W3N_sig } */
__device__ float g_Y[MAXB * 256];

/* ---------------- packed fp32x2 helpers ---------------- */
__device__ __forceinline__ u64 ffma2(u64 a, u64 b, u64 c) {
    u64 d;
    asm("fma.rn.f32x2 %0, %1, %2, %3;" : "=l"(d) : "l"(a), "l"(b), "l"(c));
    return d;
}
__device__ __forceinline__ u64 add2(u64 a, u64 b) {
    u64 d;
    asm("add.rn.f32x2 %0, %1, %2;" : "=l"(d) : "l"(a), "l"(b));
    return d;
}
__device__ __forceinline__ u64 pack2(float x, float y) {
    u64 r; asm("mov.b64 %0, {%1, %2};" : "=l"(r) : "f"(x), "f"(y)); return r;
}
__device__ __forceinline__ float2 unpack2(u64 v) {
    float x, y; asm("mov.b64 {%0, %1}, %2;" : "=f"(x), "=f"(y) : "l"(v));
    return make_float2(x, y);
}
__device__ __forceinline__ u64 relu2(u64 a) {
    float2 f = unpack2(a);
    return pack2(fmaxf(f.x, 0.f), fmaxf(f.y, 0.f));
}
__device__ __forceinline__ u64 max2(u64 A, u64 B) {
    float2 fa = unpack2(A), fb = unpack2(B);
    return pack2(fmaxf(fa.x, fb.x), fmaxf(fa.y, fb.y));
}
__device__ __forceinline__ u64 shfl64x(u64 vv, int m) {
    unsigned lo, hi;
    asm("mov.b64 {%0,%1}, %2;" : "=r"(lo), "=r"(hi) : "l"(vv));
    lo = __shfl_xor_sync(0xFFFFFFFFu, lo, m);
    hi = __shfl_xor_sync(0xFFFFFFFFu, hi, m);
    u64 r; asm("mov.b64 %0, {%1,%2};" : "=l"(r) : "r"(lo), "r"(hi));
    return r;
}

/* ---------------- main-kernel smem layout (float offsets) ----------------
   - SN quad (uv matrices): [k*128 + 4l + q] = q<2 ? S[k][2l+(q&1)] : N[k][2l+(q&1)]
   - WI2P pair-k quad: [k2*128 + 4l + q] = W[2*k2 + (q>>1)][2l + (q&1)]
   - W1B / W2B: PLAIN [k][64] (for 2D-tiled edge GEMM float4 column loads)
   - W3BD: pre-duplicated w3b u64 pairs */
#define OWI1  0          /* 192  */
#define OWI2P 192        /* 4096 */
#define OW1SN 4288       /* 8192 */
#define OW1B  12480      /* 4096 plain */
#define OW2SN 16576      /* 8192 (x-rows only; sigma hoisted to g_Y) */
#define OW2B  24768      /* 4096 plain */
#define OW3SN 28864      /* 8192 */
#define OW3BD 37056      /* 384  */
#define OBI1  37440
#define OBI2  37504
#define OB1A  37568
#define OB1B  37632
#define OB2B  37696
#define OB3B  37760      /* 3 */
#define OACT  37764      /* byte 151056, 16B-aligned */
#define WARP_ACT 832     /* u64 per warp: mh 12*64; sc at +768 */
#define NWARP 12
#define NTHR (NWARP * 32)
#define SMEM_BYTES (OACT * 4 + NWARP * WARP_ACT * 8)   /* 230,928 B <= 232,448 */

/* ================= prologue: time embedding + sigma-GEMM fold ================= */
__global__ void prep_kernel(const float* __restrict__ t, const float* __restrict__ Wf,
                            const float* __restrict__ wt, const float* __restrict__ bt,
                            const float* __restrict__ w2a, const float* __restrict__ b2a,
                            const float* __restrict__ w3a, const float* __restrict__ b3a,
                            int Bn) {
    __shared__ float swt[1024];
    __shared__ float sw2s[2048], sw2n[2048], sw3s[2048], sw3n[2048];
    __shared__ float sbt[32], swf[16], sb2[64], sb3[64];
    for (int i = threadIdx.x; i < 1024; i += 256) swt[i] = wt[i];
    for (int i = threadIdx.x; i < 2048; i += 256) {
        float a2 = w2a[4096 + i], d2 = w2a[10240 + i];
        sw2s[i] = a2 - d2; sw2n[i] = d2;
        float a3 = w3a[4096 + i], d3 = w3a[10240 + i];
        sw3s[i] = a3 - d3; sw3n[i] = d3;
    }
    if (threadIdx.x < 32) sbt[threadIdx.x] = bt[threadIdx.x];
    if (threadIdx.x < 16) swf[threadIdx.x] = Wf[threadIdx.x];
    if (threadIdx.x < 64) { sb2[threadIdx.x] = b2a[threadIdx.x]; sb3[threadIdx.x] = b3a[threadIdx.x]; }
    __syncthreads();
    int b = blockIdx.x * 256 + threadIdx.x;
    if (b >= Bn) return;
    float tb = t[b];
    float e[32];
#pragma unroll
    for (int m = 0; m < 16; m++) {
        float p = tb * swf[m] * TWO_PI;
        e[m]      = fmaxf(sinf(p), 0.f);
        e[16 + m] = fmaxf(cosf(p), 0.f);
    }
    float xs[32];
#pragma unroll 4
    for (int c = 0; c < 32; c++) {
        float a = sbt[c];
#pragma unroll
        for (int k = 0; k < 32; k++) a = fmaf(e[k], swt[k * 32 + c], a);
        xs[c] = fmaxf(a, 0.f);
    }
    float* yo = g_Y + (size_t)b * 256;
#pragma unroll 1
    for (int c = 0; c < 64; c += 4) {
        float4 aS2 = *reinterpret_cast<const float4*>(&sb2[c]);
        float4 aN2 = make_float4(0.f, 0.f, 0.f, 0.f);
        float4 aS3 = *reinterpret_cast<const float4*>(&sb3[c]);
        float4 aN3 = make_float4(0.f, 0.f, 0.f, 0.f);
#pragma unroll
        for (int k = 0; k < 32; k++) {
            float xk = xs[k];
            float4 w;
            w = *reinterpret_cast<const float4*>(&sw2s[k * 64 + c]);
            aS2.x = fmaf(xk, w.x, aS2.x); aS2.y = fmaf(xk, w.y, aS2.y);
            aS2.z = fmaf(xk, w.z, aS2.z); aS2.w = fmaf(xk, w.w, aS2.w);
            w = *reinterpret_cast<const float4*>(&sw2n[k * 64 + c]);
            aN2.x = fmaf(xk, w.x, aN2.x); aN2.y = fmaf(xk, w.y, aN2.y);
            aN2.z = fmaf(xk, w.z, aN2.z); aN2.w = fmaf(xk, w.w, aN2.w);
            w = *reinterpret_cast<const float4*>(&sw3s[k * 64 + c]);
            aS3.x = fmaf(xk, w.x, aS3.x); aS3.y = fmaf(xk, w.y, aS3.y);
            aS3.z = fmaf(xk, w.z, aS3.z); aS3.w = fmaf(xk, w.w, aS3.w);
            w = *reinterpret_cast<const float4*>(&sw3n[k * 64 + c]);
            aN3.x = fmaf(xk, w.x, aN3.x); aN3.y = fmaf(xk, w.y, aN3.y);
            aN3.z = fmaf(xk, w.z, aN3.z); aN3.w = fmaf(xk, w.w, aN3.w);
        }
        *reinterpret_cast<float4*>(&yo[c])       = aS2;
        *reinterpret_cast<float4*>(&yo[64 + c])  = aN2;
        *reinterpret_cast<float4*>(&yo[128 + c]) = aS3;
        *reinterpret_cast<float4*>(&yo[192 + c]) = aN3;
    }
}

/* ======= uv accumulate over 64 x-columns; SN-quad weights (R9 form) ======= */
__device__ __forceinline__ void uv64(const u64* __restrict__ xq,
                                     const float* __restrict__ WSN,
                                     int l, u64 (&u)[7][2], u64 (&v)[7][2]) {
    const float* wp = WSN + 4 * l;
#pragma unroll 1
    for (int k = 0; k < 64; k += 2) {
        float4 wa = *reinterpret_cast<const float4*>(&wp[k * 128]);
        float4 wb = *reinterpret_cast<const float4*>(&wp[(k + 1) * 128]);
        u64 s00 = pack2(wa.x, wa.x), s01 = pack2(wa.y, wa.y);
        u64 n00 = pack2(wa.z, wa.z), n01 = pack2(wa.w, wa.w);
        u64 s10 = pack2(wb.x, wb.x), s11 = pack2(wb.y, wb.y);
        u64 n10 = pack2(wb.z, wb.z), n11 = pack2(wb.w, wb.w);
#pragma unroll
        for (int n = 0; n < 7; n++) {
            ulonglong2 xv = *reinterpret_cast<const ulonglong2*>(&xq[n * 64 + k]);
            u[n][0] = ffma2(xv.x, s00, u[n][0]);
            u[n][1] = ffma2(xv.x, s01, u[n][1]);
            v[n][0] = ffma2(xv.x, n00, v[n][0]);
            v[n][1] = ffma2(xv.x, n01, v[n][1]);
            u[n][0] = ffma2(xv.y, s10, u[n][0]);
            u[n][1] = ffma2(xv.y, s11, u[n][1]);
            v[n][0] = ffma2(xv.y, n10, v[n][0]);
            v[n][1] = ffma2(xv.y, n11, v[n][1]);
        }
    }
}

/* === 2D-tiled edge group: 2 destination nodes, lanes = 4 row-groups x 8 cols.
   Msg loads: 3 LDS.128/k-pair (4 distinct rg addrs each) instead of 12 broadcasts.
   Dot-product k-order and max-fold values identical to the column version. === */
template <int I0>
__device__ __forceinline__ void edge2d(u64* __restrict__ mh, const float* __restrict__ wb,
                                       float4 bb0, float4 bb1, int l, int rg, int cg,
                                       u64 (&u)[7][2], const u64 (&v)[7][2]) {
    __syncwarp();
#pragma unroll
    for (int ig = 0; ig < 2; ig++) {
        const int i = I0 + ig;
#pragma unroll
        for (int j = 0; j < 7; j++) {
            if (j == i) continue;
            const int jj = (j < i) ? j : j - 1;
            ulonglong2 mm;
            mm.x = relu2(add2(u[i][0], v[j][0]));
            mm.y = relu2(add2(u[i][1], v[j][1]));
            *reinterpret_cast<ulonglong2*>(&mh[(ig * 6 + jj) * 64 + 2 * l]) = mm;
        }
    }
    __syncwarp();
    u64 a[3][8];
#pragma unroll
    for (int r = 0; r < 3; r++)
#pragma unroll
        for (int c = 0; c < 8; c++) a[r][c] = 0ULL;
    const u64* mrow = mh + rg * 192;        /* rows rg*3 .. rg*3+2 */
    const float* wc = wb + 8 * cg;          /* cols 8cg .. 8cg+7   */
#pragma unroll 1
    for (int k = 0; k < 64; k += 2) {
        ulonglong2 m0 = *reinterpret_cast<const ulonglong2*>(mrow + k);
        ulonglong2 m1 = *reinterpret_cast<const ulonglong2*>(mrow + 64 + k);
        ulonglong2 m2 = *reinterpret_cast<const ulonglong2*>(mrow + 128 + k);
        float4 wA0 = *reinterpret_cast<const float4*>(wc + k * 64);
        float4 wA1 = *reinterpret_cast<const float4*>(wc + k * 64 + 4);
        float4 wB0 = *reinterpret_cast<const float4*>(wc + (k + 1) * 64);
        float4 wB1 = *reinterpret_cast<const float4*>(wc + (k + 1) * 64 + 4);
#define COLFMA(WLO, WHI, CI) do {                                   \
        u64 _wk  = pack2(WLO, WLO);                                 \
        u64 _wk1 = pack2(WHI, WHI);                                 \
        a[0][CI] = ffma2(m0.x, _wk,  a[0][CI]);                     \
        a[0][CI] = ffma2(m0.y, _wk1, a[0][CI]);                     \
        a[1][CI] = ffma2(m1.x, _wk,  a[1][CI]);                     \
        a[1][CI] = ffma2(m1.y, _wk1, a[1][CI]);                     \
        a[2][CI] = ffma2(m2.x, _wk,  a[2][CI]);                     \
        a[2][CI] = ffma2(m2.y, _wk1, a[2][CI]);                     \
    } while (0)
        COLFMA(wA0.x, wB0.x, 0); COLFMA(wA0.y, wB0.y, 1);
        COLFMA(wA0.z, wB0.z, 2); COLFMA(wA0.w, wB0.w, 3);
        COLFMA(wA1.x, wB1.x, 4); COLFMA(wA1.y, wB1.y, 5);
        COLFMA(wA1.z, wB1.z, 6); COLFMA(wA1.w, wB1.w, 7);
#undef COLFMA
    }
    /* max over this lane's 3 rows, then cross row-group (xor 8), bias, relu */
    u64 m8[8];
#pragma unroll
    for (int c = 0; c < 8; c++)
        m8[c] = max2(max2(a[0][c], a[1][c]), a[2][c]);
#pragma unroll
    for (int c = 0; c < 8; c++)
        m8[c] = max2(m8[c], shfl64x(m8[c], 8));
    const float bc[8] = {bb0.x, bb0.y, bb0.z, bb0.w, bb1.x, bb1.y, bb1.z, bb1.w};
#pragma unroll
    for (int c = 0; c < 8; c++)
        m8[c] = relu2(add2(m8[c], pack2(bc[c], bc[c])));
    /* redistribute to column layout via smem (rg0 -> i0 buf, rg2 -> i1 buf) */
    __syncwarp();
    if ((rg & 1) == 0) {
        u64* buf = mh + ((rg == 0) ? 0 : 384);
        ulonglong2 s;
        s.x = m8[0]; s.y = m8[1]; *reinterpret_cast<ulonglong2*>(&buf[8 * cg])     = s;
        s.x = m8[2]; s.y = m8[3]; *reinterpret_cast<ulonglong2*>(&buf[8 * cg + 2]) = s;
        s.x = m8[4]; s.y = m8[5]; *reinterpret_cast<ulonglong2*>(&buf[8 * cg + 4]) = s;
        s.x = m8[6]; s.y = m8[7]; *reinterpret_cast<ulonglong2*>(&buf[8 * cg + 6]) = s;
    }
    __syncwarp();
    ulonglong2 r0 = *reinterpret_cast<const ulonglong2*>(&mh[2 * l]);
    u[I0][0] = r0.x; u[I0][1] = r0.y;
    ulonglong2 r1 = *reinterpret_cast<const ulonglong2*>(&mh[384 + 2 * l]);
    u[I0 + 1][0] = r1.x; u[I0 + 1][1] = r1.y;
}

/* === last destination node (i=6), column-style, plain weights === */
__device__ __forceinline__ void edge_one6(u64* __restrict__ mh, const float* __restrict__ wb,
                                          const float* __restrict__ BB, int l,
                                          u64 (&u)[7][2], const u64 (&v)[7][2]) {
    float2 bb = *reinterpret_cast<const float2*>(&BB[2 * l]);
    __syncwarp();
#pragma unroll
    for (int j = 0; j < 6; j++) {
        ulonglong2 mm;
        mm.x = relu2(add2(u[6][0], v[j][0]));
        mm.y = relu2(add2(u[6][1], v[j][1]));
        *reinterpret_cast<ulonglong2*>(&mh[j * 64 + 2 * l]) = mm;
    }
    __syncwarp();
    u64 a[6][2];
#pragma unroll
    for (int jj = 0; jj < 6; jj++) { a[jj][0] = 0ULL; a[jj][1] = 0ULL; }
#pragma unroll 1
    for (int k = 0; k < 64; k += 2) {
        float2 w0 = *reinterpret_cast<const float2*>(&wb[k * 64 + 2 * l]);
        float2 w1 = *reinterpret_cast<const float2*>(&wb[(k + 1) * 64 + 2 * l]);
        u64 wx0 = pack2(w0.x, w0.x), wy0 = pack2(w0.y, w0.y);
        u64 wx1 = pack2(w1.x, w1.x), wy1 = pack2(w1.y, w1.y);
#pragma unroll
        for (int jj = 0; jj < 6; jj++) {
            ulonglong2 mv = *reinterpret_cast<const ulonglong2*>(&mh[jj * 64 + k]);
            a[jj][0] = ffma2(mv.x, wx0, a[jj][0]);
            a[jj][1] = ffma2(mv.x, wy0, a[jj][1]);
            a[jj][0] = ffma2(mv.y, wx1, a[jj][0]);
            a[jj][1] = ffma2(mv.y, wy1, a[jj][1]);
        }
    }
#pragma unroll
    for (int cc = 0; cc < 2; cc++) {
        float2 m = unpack2(a[0][cc]);
#pragma unroll
        for (int jj = 1; jj < 6; jj++) {
            float2 q = unpack2(a[jj][cc]);
            m.x = fmaxf(m.x, q.x); m.y = fmaxf(m.y, q.y);
        }
        float b = cc ? bb.y : bb.x;
        u[6][cc] = pack2(fmaxf(m.x + b, 0.f), fmaxf(m.y + b, 0.f));
    }
}

__device__ __forceinline__ void edge64(u64* __restrict__ mh, const float* __restrict__ wb,
                                       const float* __restrict__ BB, int l, int rg, int cg,
                                       u64 (&u)[7][2], const u64 (&v)[7][2]) {
    float4 bb0 = *reinterpret_cast<const float4*>(&BB[8 * cg]);
    float4 bb1 = *reinterpret_cast<const float4*>(&BB[8 * cg + 4]);
    edge2d<0>(mh, wb, bb0, bb1, l, rg, cg, u, v);
    edge2d<2>(mh, wb, bb0, bb1, l, rg, cg, u, v);
    edge2d<4>(mh, wb, bb0, bb1, l, rg, cg, u, v);
    edge_one6(mh, wb, BB, l, u, v);
}

/* ================= main fused GNN: one warp per pair of graphs ================= */
__global__ __launch_bounds__(NTHR, 1)
void gnn_main(const float* __restrict__ omega, const float* __restrict__ t,
              const float* __restrict__ wi1, const float* __restrict__ bi1,
              const float* __restrict__ wi2, const float* __restrict__ bi2,
              const float* __restrict__ w1a, const float* __restrict__ b1a,
              const float* __restrict__ w1b, const float* __restrict__ b1b,
              const float* __restrict__ w2a, const float* __restrict__ b2a,
              const float* __restrict__ w2b, const float* __restrict__ b2b,
              const float* __restrict__ w3a, const float* __restrict__ b3a,
              const float* __restrict__ w3b, const float* __restrict__ b3b,
              float* __restrict__ out, int Bn) {
    extern __shared__ float sm[];
    const int tid = threadIdx.x;

    /* ---- weight prologue ---- */
    for (int o = tid; o < 4096; o += NTHR) {
        int k2 = o >> 7, l4 = (o >> 2) & 31, q = o & 3;
        int k = 2 * k2 + (q >> 1), c = 2 * l4 + (q & 1);
        sm[OWI2P + o] = wi2[k * 64 + c];
        sm[OW1B + o] = w1b[o];          /* plain */
        sm[OW2B + o] = w2b[o];          /* plain */
    }
    for (int o = tid; o < 8192; o += NTHR) {
        int k = o >> 7, l4 = (o >> 2) & 31, q = o & 3;
        int c = 2 * l4 + (q & 1);
        float t1 = w1a[k * 64 + c], b1_ = w1a[4096 + k * 64 + c];
        sm[OW1SN + o] = (q < 2) ? (t1 - b1_) : b1_;
        float t2 = w2a[k * 64 + c], b2_ = w2a[6144 + k * 64 + c];
        sm[OW2SN + o] = (q < 2) ? (t2 - b2_) : b2_;
        float t3 = w3a[k * 64 + c], b3_ = w3a[6144 + k * 64 + c];
        sm[OW3SN + o] = (q < 2) ? (t3 - b3_) : b3_;
    }
    for (int i = tid; i < 192; i += NTHR) {
        sm[OWI1 + i] = wi1[i];
        float wv = w3b[i];
        sm[OW3BD + 2 * i]     = wv;
        sm[OW3BD + 2 * i + 1] = wv;
    }
    if (tid < 64) {
        sm[OBI1 + tid] = bi1[tid]; sm[OBI2 + tid] = bi2[tid];
        sm[OB1A + tid] = b1a[tid]; sm[OB1B + tid] = b1b[tid];
        sm[OB2B + tid] = b2b[tid];
    }
    if (tid < 3) sm[OB3B + tid] = b3b[tid];
    __syncthreads();

    const int w = tid >> 5, l = tid & 31;
    const int rg = l >> 3, cg = l & 7;
    u64* const x64 = reinterpret_cast<u64*>(sm + OACT) + w * WARP_ACT;
    u64* const mh  = x64;          /* edge-phase msg buffer (12 rows) aliases old x */
    u64* const sc  = x64 + 768;    /* layer-3 reduce scratch (18 u64)     */

    const float* WI1f = sm + OWI1;

    const int npairs = (Bn + 1) >> 1;
    const int jj3 = l / 3, c3 = l - 3 * jj3;

    u64 u[7][2], v[7][2];

    for (int p = blockIdx.x * NWARP + w; p < npairs; p += gridDim.x * NWARP) {
        const int gA = 2 * p;
        const int gB = (2 * p + 1 < Bn) ? (2 * p + 1) : gA;
        __syncwarp();

        /* per-graph 1/(std+1e-7) */
        const float tA = t[gA], tB = t[gB];
        const float invA = 1.f / (sqrtf((expf(2.f * tA * LN_SIGMA) - 1.f) / (2.f * LN_SIGMA)) + 1e-7f);
        const float invB = 1.f / (sqrtf((expf(2.f * tB * LN_SIGMA) - 1.f) / (2.f * LN_SIGMA)) + 1e-7f);

        /* sigma row indices (tile-quirk: (g*7+n) % B) */
        int ia[7], ib[7];
        {
            int rA = (gA * 7) % Bn, rB = (gB * 7) % Bn;
#pragma unroll
            for (int n = 0; n < 7; n++) {
                int a_ = rA + n; ia[n] = (a_ >= Bn) ? a_ - Bn : a_;
                int b_ = rB + n; ib[n] = (b_ >= Bn) ? b_ - Bn : b_;
            }
        }

        /* ---- init features: hid1 -> x64 scratch; hid2 -> regs -> x64 ---- */
        {
            float2 wd0 = *reinterpret_cast<const float2*>(&WI1f[0 * 64 + 2 * l]);
            float2 wd1 = *reinterpret_cast<const float2*>(&WI1f[1 * 64 + 2 * l]);
            float2 wd2 = *reinterpret_cast<const float2*>(&WI1f[2 * 64 + 2 * l]);
            float2 bb  = *reinterpret_cast<const float2*>(&sm[OBI1 + 2 * l]);
            u64 w0x = pack2(wd0.x, wd0.x), w0y = pack2(wd0.y, wd0.y);
            u64 w1x = pack2(wd1.x, wd1.x), w1y = pack2(wd1.y, wd1.y);
            u64 w2x = pack2(wd2.x, wd2.x), w2y = pack2(wd2.y, wd2.y);
#pragma unroll
            for (int n = 0; n < 7; n++) {
                const float* oA = omega + (size_t)(gA * 7 + n) * 3;
                const float* oB = omega + (size_t)(gB * 7 + n) * 3;
                u64 p0 = pack2(oA[0], oB[0]);
                u64 p1 = pack2(oA[1], oB[1]);
                u64 p2 = pack2(oA[2], oB[2]);
                u64 h0 = pack2(bb.x, bb.x), h1 = pack2(bb.y, bb.y);
                h0 = ffma2(p0, w0x, h0); h0 = ffma2(p1, w1x, h0); h0 = ffma2(p2, w2x, h0);
                h1 = ffma2(p0, w0y, h1); h1 = ffma2(p1, w1y, h1); h1 = ffma2(p2, w2y, h1);
                ulonglong2 hh; hh.x = relu2(h0); hh.y = relu2(h1);
                *reinterpret_cast<ulonglong2*>(&x64[n * 64 + 2 * l]) = hh;
            }
        }
        __syncwarp();
        {
            float2 bi = *reinterpret_cast<const float2*>(&sm[OBI2 + 2 * l]);
#pragma unroll
            for (int n = 0; n < 7; n++) {
                u[n][0] = pack2(bi.x, bi.x); u[n][1] = pack2(bi.y, bi.y);
            }
            const float* wp = sm + OWI2P + 4 * l;
#pragma unroll 1
            for (int k = 0; k < 64; k += 2) {
                float4 wv = *reinterpret_cast<const float4*>(&wp[k * 64]);
                u64 wx0 = pack2(wv.x, wv.x), wy0 = pack2(wv.y, wv.y);
                u64 wx1 = pack2(wv.z, wv.z), wy1 = pack2(wv.w, wv.w);
#pragma unroll
                for (int n = 0; n < 7; n++) {
                    ulonglong2 hv = *reinterpret_cast<const ulonglong2*>(&x64[n * 64 + k]);
                    u[n][0] = ffma2(hv.x, wx0, u[n][0]);
                    u[n][1] = ffma2(hv.x, wy0, u[n][1]);
                    u[n][0] = ffma2(hv.y, wx1, u[n][0]);
                    u[n][1] = ffma2(hv.y, wy1, u[n][1]);
                }
            }
        }
        __syncwarp();
#pragma unroll
        for (int n = 0; n < 7; n++) {
            ulonglong2 xx; xx.x = u[n][0]; xx.y = u[n][1];
            *reinterpret_cast<ulonglong2*>(&x64[n * 64 + 2 * l]) = xx;
        }
        __syncwarp();

        /* ---- layer 1: init u=bias, v=0 ---- */
        {
            float2 ba = *reinterpret_cast<const float2*>(&sm[OB1A + 2 * l]);
#pragma unroll
            for (int n = 0; n < 7; n++) {
                u[n][0] = pack2(ba.x, ba.x); u[n][1] = pack2(ba.y, ba.y);
                v[n][0] = 0ULL;              v[n][1] = 0ULL;
            }
        }
        uv64(x64, sm + OW1SN, l, u, v);
        edge64(mh, sm + OW1B, sm + OB1B, l, rg, cg, u, v);
        __syncwarp();
#pragma unroll
        for (int n = 0; n < 7; n++) {
            ulonglong2 xx; xx.x = u[n][0]; xx.y = u[n][1];
            *reinterpret_cast<ulonglong2*>(&x64[n * 64 + 2 * l]) = xx;
        }
        __syncwarp();

        /* ---- layer 2: init u,v from precomputed sigma contributions ---- */
#pragma unroll
        for (int n = 0; n < 7; n++) {
            const float* yA = g_Y + (size_t)ia[n] * 256;
            const float* yB = g_Y + (size_t)ib[n] * 256;
            float2 sA = *reinterpret_cast<const float2*>(&yA[2 * l]);
            float2 sB = *reinterpret_cast<const float2*>(&yB[2 * l]);
            float2 nA = *reinterpret_cast<const float2*>(&yA[64 + 2 * l]);
            float2 nB = *reinterpret_cast<const float2*>(&yB[64 + 2 * l]);
            u[n][0] = pack2(sA.x, sB.x); u[n][1] = pack2(sA.y, sB.y);
            v[n][0] = pack2(nA.x, nB.x); v[n][1] = pack2(nA.y, nB.y);
        }
        uv64(x64, sm + OW2SN, l, u, v);
        edge64(mh, sm + OW2B, sm + OB2B, l, rg, cg, u, v);
        __syncwarp();
#pragma unroll
        for (int n = 0; n < 7; n++) {
            ulonglong2 xx; xx.x = u[n][0]; xx.y = u[n][1];
            *reinterpret_cast<ulonglong2*>(&x64[n * 64 + 2 * l]) = xx;
        }
        __syncwarp();

        /* ---- layer 3: init from Y, uv, 3-wide edge output ---- */
#pragma unroll
        for (int n = 0; n < 7; n++) {
            const float* yA = g_Y + (size_t)ia[n] * 256;
            const float* yB = g_Y + (size_t)ib[n] * 256;
            float2 sA = *reinterpret_cast<const float2*>(&yA[128 + 2 * l]);
            float2 sB = *reinterpret_cast<const float2*>(&yB[128 + 2 * l]);
            float2 nA = *reinterpret_cast<const float2*>(&yA[192 + 2 * l]);
            float2 nB = *reinterpret_cast<const float2*>(&yB[192 + 2 * l]);
            u[n][0] = pack2(sA.x, sB.x); u[n][1] = pack2(sA.y, sB.y);
            v[n][0] = pack2(nA.x, nB.x); v[n][1] = pack2(nA.y, nB.y);
        }
        uv64(x64, sm + OW3SN, l, u, v);
#pragma unroll
        for (int i = 0; i < 7; i++) {
            __syncwarp();
#pragma unroll
            for (int j = 0; j < 7; j++) {
                if (j == i) continue;
                const int jj = (j < i) ? j : j - 1;
                ulonglong2 mm;
                mm.x = relu2(add2(u[i][0], v[j][0]));
                mm.y = relu2(add2(u[i][1], v[j][1]));
                *reinterpret_cast<ulonglong2*>(&mh[jj * 64 + 2 * l]) = mm;
            }
            __syncwarp();
            if (l < 18) {
                u64 acc = 0ULL;
                const float* wdp = sm + OW3BD;
#pragma unroll 1
                for (int k = 0; k < 64; k += 2) {
                    ulonglong2 mv = *reinterpret_cast<const ulonglong2*>(&mh[jj3 * 64 + k]);
                    u64 wd0 = *reinterpret_cast<const u64*>(&wdp[2 * (k * 3 + c3)]);
                    u64 wd1 = *reinterpret_cast<const u64*>(&wdp[2 * ((k + 1) * 3 + c3)]);
                    acc = ffma2(mv.x, wd0, acc);
                    acc = ffma2(mv.y, wd1, acc);
                }
                sc[l] = acc;
            }
            __syncwarp();
            if (l < 3) {
                float2 m = unpack2(sc[l]);
#pragma unroll
                for (int jq = 1; jq < 6; jq++) {
                    float2 q = unpack2(sc[jq * 3 + l]);
                    m.x = fmaxf(m.x, q.x); m.y = fmaxf(m.y, q.y);
                }
                float b3 = sm[OB3B + l];
                out[(size_t)(gA * 7 + i) * 3 + l] = (m.x + b3) * invA;
                out[(size_t)(gB * 7 + i) * 3 + l] = (m.y + b3) * invB;
            }
        }
    }
}

extern "C" void kernel_launch(void* const* d_in, const int* in_sizes, int n_in,
                              void* d_out, int out_size) {
    const float* omega = (const float*)d_in[0];
    /* d_in[1] edge_index (fixed all-pairs; computed implicitly), d_in[3] num_objs unused */
    const float* t   = (const float*)d_in[2];
    const float* Wf  = (const float*)d_in[4];
    const float* wi1 = (const float*)d_in[5];  const float* bi1 = (const float*)d_in[6];
    const float* wi2 = (const float*)d_in[7];  const float* bi2 = (const float*)d_in[8];
    const float* wt  = (const float*)d_in[9];  const float* bt  = (const float*)d_in[10];
    const float* w1a = (const float*)d_in[11]; const float* b1a = (const float*)d_in[12];
    const float* w1b = (const float*)d_in[13]; const float* b1b = (const float*)d_in[14];
    const float* w2a = (const float*)d_in[15]; const float* b2a = (const float*)d_in[16];
    const float* w2b = (const float*)d_in[17]; const float* b2b = (const float*)d_in[18];
    const float* w3a = (const float*)d_in[19]; const float* b3a = (const float*)d_in[20];
    const float* w3b = (const float*)d_in[21]; const float* b3b = (const float*)d_in[22];
    float* out = (float*)d_out;

    int Bn = in_sizes[2];
    if (Bn > MAXB) Bn = MAXB;

    prep_kernel<<<(Bn + 255) / 256, 256>>>(t, Wf, wt, bt, w2a, b2a, w3a, b3a, Bn);

    cudaFuncSetAttribute(gnn_main, cudaFuncAttributeMaxDynamicSharedMemorySize, SMEM_BYTES);
    int dev = 0, nsm = 148;
    cudaGetDevice(&dev);
    cudaDeviceGetAttribute(&nsm, cudaDevAttrMultiProcessorCount, dev);

    gnn_main<<<nsm, NTHR, SMEM_BYTES>>>(omega, t, wi1, bi1, wi2, bi2,
                                        w1a, b1a, w1b, b1b,
                                        w2a, b2a, w2b, b2b,
                                        w3a, b3a, w3b, b3b, out, Bn);
}

// round 13
// speedup vs baseline: 1.1217x; 1.1217x over previous
#include <cuda_runtime.h>
#include <cuda_bf16.h>

typedef unsigned long long u64;

#define NOBJ 7
#define MAXB 50000
#define TWO_PI 6.283185307179586f
#define LN_SIGMA 3.2188758248682006f   /* ln(25) */
#define MST 66   /* padded msg-row stride (u64): 528B, kills 512B bank aliasing */

/* precomputed sigma contributions: Y[b][4][64] =
   { xs_b@W2S_sig + b2a, xs_b@W2N_sig, xs_b@W3S_sig + b3a, xs_b@W3N_sig } */
__device__ float g_Y[MAXB * 256];

/* ---------------- packed fp32x2 helpers ---------------- */
__device__ __forceinline__ u64 ffma2(u64 a, u64 b, u64 c) {
    u64 d;
    asm("fma.rn.f32x2 %0, %1, %2, %3;" : "=l"(d) : "l"(a), "l"(b), "l"(c));
    return d;
}
__device__ __forceinline__ u64 add2(u64 a, u64 b) {
    u64 d;
    asm("add.rn.f32x2 %0, %1, %2;" : "=l"(d) : "l"(a), "l"(b));
    return d;
}
__device__ __forceinline__ u64 pack2(float x, float y) {
    u64 r; asm("mov.b64 %0, {%1, %2};" : "=l"(r) : "f"(x), "f"(y)); return r;
}
__device__ __forceinline__ float2 unpack2(u64 v) {
    float x, y; asm("mov.b64 {%0, %1}, %2;" : "=f"(x), "=f"(y) : "l"(v));
    return make_float2(x, y);
}
__device__ __forceinline__ u64 relu2(u64 a) {
    float2 f = unpack2(a);
    return pack2(fmaxf(f.x, 0.f), fmaxf(f.y, 0.f));
}
__device__ __forceinline__ u64 max2(u64 A, u64 B) {
    float2 fa = unpack2(A), fb = unpack2(B);
    return pack2(fmaxf(fa.x, fb.x), fmaxf(fa.y, fb.y));
}
__device__ __forceinline__ u64 shfl64x(u64 vv, int m) {
    unsigned lo, hi;
    asm("mov.b64 {%0,%1}, %2;" : "=r"(lo), "=r"(hi) : "l"(vv));
    lo = __shfl_xor_sync(0xFFFFFFFFu, lo, m);
    hi = __shfl_xor_sync(0xFFFFFFFFu, hi, m);
    u64 r; asm("mov.b64 %0, {%1,%2};" : "=l"(r) : "r"(lo), "r"(hi));
    return r;
}

/* ---------------- main-kernel smem layout (float offsets) ----------------
   - SN quad (uv matrices): [k*128 + 4l + q] = q<2 ? S[k][2l+(q&1)] : N[k][2l+(q&1)]
   - WI2P pair-k quad: [k2*128 + 4l + q] = W[2*k2 + (q>>1)][2l + (q&1)]
   - W1B / W2B: PLAIN [k][64] (2D-tiled edge GEMM float4 column loads)
   - W3BD: pre-duplicated w3b u64 pairs */
#define OWI1  0          /* 192  */
#define OWI2P 192        /* 4096 */
#define OW1SN 4288       /* 8192 */
#define OW1B  12480      /* 4096 plain */
#define OW2SN 16576      /* 8192 (x-rows only; sigma hoisted to g_Y) */
#define OW2B  24768      /* 4096 plain */
#define OW3SN 28864      /* 8192 */
#define OW3BD 37056      /* 384  */
#define OBI1  37440
#define OBI2  37504
#define OB1A  37568
#define OB1B  37632
#define OB2B  37696
#define OB3B  37760      /* 3 */
#define OACT  37764      /* byte 151056, 16B-aligned */
#define WARP_ACT 832     /* u64/warp: x 7*64 | mh 12*MST=792 (alias) | sc at +792 */
#define NWARP 12
#define NTHR (NWARP * 32)
#define SMEM_BYTES (OACT * 4 + NWARP * WARP_ACT * 8)   /* 230,928 B <= 232,448 */

/* ================= prologue: time embedding + sigma-GEMM fold ================= */
__global__ void prep_kernel(const float* __restrict__ t, const float* __restrict__ Wf,
                            const float* __restrict__ wt, const float* __restrict__ bt,
                            const float* __restrict__ w2a, const float* __restrict__ b2a,
                            const float* __restrict__ w3a, const float* __restrict__ b3a,
                            int Bn) {
    __shared__ float swt[1024];
    __shared__ float sw2s[2048], sw2n[2048], sw3s[2048], sw3n[2048];
    __shared__ float sbt[32], swf[16], sb2[64], sb3[64];
    for (int i = threadIdx.x; i < 1024; i += 256) swt[i] = wt[i];
    for (int i = threadIdx.x; i < 2048; i += 256) {
        float a2 = w2a[4096 + i], d2 = w2a[10240 + i];
        sw2s[i] = a2 - d2; sw2n[i] = d2;
        float a3 = w3a[4096 + i], d3 = w3a[10240 + i];
        sw3s[i] = a3 - d3; sw3n[i] = d3;
    }
    if (threadIdx.x < 32) sbt[threadIdx.x] = bt[threadIdx.x];
    if (threadIdx.x < 16) swf[threadIdx.x] = Wf[threadIdx.x];
    if (threadIdx.x < 64) { sb2[threadIdx.x] = b2a[threadIdx.x]; sb3[threadIdx.x] = b3a[threadIdx.x]; }
    __syncthreads();
    int b = blockIdx.x * 256 + threadIdx.x;
    if (b >= Bn) return;
    float tb = t[b];
    float e[32];
#pragma unroll
    for (int m = 0; m < 16; m++) {
        float p = tb * swf[m] * TWO_PI;
        e[m]      = fmaxf(sinf(p), 0.f);
        e[16 + m] = fmaxf(cosf(p), 0.f);
    }
    float xs[32];
#pragma unroll 4
    for (int c = 0; c < 32; c++) {
        float a = sbt[c];
#pragma unroll
        for (int k = 0; k < 32; k++) a = fmaf(e[k], swt[k * 32 + c], a);
        xs[c] = fmaxf(a, 0.f);
    }
    float* yo = g_Y + (size_t)b * 256;
#pragma unroll 1
    for (int c = 0; c < 64; c += 4) {
        float4 aS2 = *reinterpret_cast<const float4*>(&sb2[c]);
        float4 aN2 = make_float4(0.f, 0.f, 0.f, 0.f);
        float4 aS3 = *reinterpret_cast<const float4*>(&sb3[c]);
        float4 aN3 = make_float4(0.f, 0.f, 0.f, 0.f);
#pragma unroll
        for (int k = 0; k < 32; k++) {
            float xk = xs[k];
            float4 w;
            w = *reinterpret_cast<const float4*>(&sw2s[k * 64 + c]);
            aS2.x = fmaf(xk, w.x, aS2.x); aS2.y = fmaf(xk, w.y, aS2.y);
            aS2.z = fmaf(xk, w.z, aS2.z); aS2.w = fmaf(xk, w.w, aS2.w);
            w = *reinterpret_cast<const float4*>(&sw2n[k * 64 + c]);
            aN2.x = fmaf(xk, w.x, aN2.x); aN2.y = fmaf(xk, w.y, aN2.y);
            aN2.z = fmaf(xk, w.z, aN2.z); aN2.w = fmaf(xk, w.w, aN2.w);
            w = *reinterpret_cast<const float4*>(&sw3s[k * 64 + c]);
            aS3.x = fmaf(xk, w.x, aS3.x); aS3.y = fmaf(xk, w.y, aS3.y);
            aS3.z = fmaf(xk, w.z, aS3.z); aS3.w = fmaf(xk, w.w, aS3.w);
            w = *reinterpret_cast<const float4*>(&sw3n[k * 64 + c]);
            aN3.x = fmaf(xk, w.x, aN3.x); aN3.y = fmaf(xk, w.y, aN3.y);
            aN3.z = fmaf(xk, w.z, aN3.z); aN3.w = fmaf(xk, w.w, aN3.w);
        }
        *reinterpret_cast<float4*>(&yo[c])       = aS2;
        *reinterpret_cast<float4*>(&yo[64 + c])  = aN2;
        *reinterpret_cast<float4*>(&yo[128 + c]) = aS3;
        *reinterpret_cast<float4*>(&yo[192 + c]) = aN3;
    }
}

/* ======= uv accumulate over 64 x-columns; SN-quad weights (R9 form) ======= */
__device__ __forceinline__ void uv64(const u64* __restrict__ xq,
                                     const float* __restrict__ WSN,
                                     int l, u64 (&u)[7][2], u64 (&v)[7][2]) {
    const float* wp = WSN + 4 * l;
#pragma unroll 1
    for (int k = 0; k < 64; k += 2) {
        float4 wa = *reinterpret_cast<const float4*>(&wp[k * 128]);
        float4 wb = *reinterpret_cast<const float4*>(&wp[(k + 1) * 128]);
        u64 s00 = pack2(wa.x, wa.x), s01 = pack2(wa.y, wa.y);
        u64 n00 = pack2(wa.z, wa.z), n01 = pack2(wa.w, wa.w);
        u64 s10 = pack2(wb.x, wb.x), s11 = pack2(wb.y, wb.y);
        u64 n10 = pack2(wb.z, wb.z), n11 = pack2(wb.w, wb.w);
#pragma unroll
        for (int n = 0; n < 7; n++) {
            ulonglong2 xv = *reinterpret_cast<const ulonglong2*>(&xq[n * 64 + k]);
            u[n][0] = ffma2(xv.x, s00, u[n][0]);
            u[n][1] = ffma2(xv.x, s01, u[n][1]);
            v[n][0] = ffma2(xv.x, n00, v[n][0]);
            v[n][1] = ffma2(xv.x, n01, v[n][1]);
            u[n][0] = ffma2(xv.y, s10, u[n][0]);
            u[n][1] = ffma2(xv.y, s11, u[n][1]);
            v[n][0] = ffma2(xv.y, n10, v[n][0]);
            v[n][1] = ffma2(xv.y, n11, v[n][1]);
        }
    }
}

/* === 2D-tiled edge group: 2 destination nodes, lanes = 4 row-groups x 8 cols.
   Msg rows padded to MST u64 (528B): the 4 rg addresses land in disjoint bank
   ranges -> conflict-free. 3 msg LDS.128 + 4 weight LDS.128 per k-pair.     === */
template <int I0>
__device__ __forceinline__ void edge2d(u64* __restrict__ mh, const float* __restrict__ wb,
                                       float4 bb0, float4 bb1, int l, int rg, int cg,
                                       u64 (&u)[7][2], const u64 (&v)[7][2]) {
    __syncwarp();
#pragma unroll
    for (int ig = 0; ig < 2; ig++) {
        const int i = I0 + ig;
#pragma unroll
        for (int j = 0; j < 7; j++) {
            if (j == i) continue;
            const int jj = (j < i) ? j : j - 1;
            ulonglong2 mm;
            mm.x = relu2(add2(u[i][0], v[j][0]));
            mm.y = relu2(add2(u[i][1], v[j][1]));
            *reinterpret_cast<ulonglong2*>(&mh[(ig * 6 + jj) * MST + 2 * l]) = mm;
        }
    }
    __syncwarp();
    u64 a[3][8];
#pragma unroll
    for (int r = 0; r < 3; r++)
#pragma unroll
        for (int c = 0; c < 8; c++) a[r][c] = 0ULL;
    const u64* mrow = mh + rg * 3 * MST;    /* rows rg*3 .. rg*3+2 */
    const float* wc = wb + 8 * cg;          /* cols 8cg .. 8cg+7   */
#pragma unroll 1
    for (int k = 0; k < 64; k += 2) {
        ulonglong2 m0 = *reinterpret_cast<const ulonglong2*>(mrow + k);
        ulonglong2 m1 = *reinterpret_cast<const ulonglong2*>(mrow + MST + k);
        ulonglong2 m2 = *reinterpret_cast<const ulonglong2*>(mrow + 2 * MST + k);
        float4 wA0 = *reinterpret_cast<const float4*>(wc + k * 64);
        float4 wA1 = *reinterpret_cast<const float4*>(wc + k * 64 + 4);
        float4 wB0 = *reinterpret_cast<const float4*>(wc + (k + 1) * 64);
        float4 wB1 = *reinterpret_cast<const float4*>(wc + (k + 1) * 64 + 4);
#define COLFMA(WLO, WHI, CI) do {                                   \
        u64 _wk  = pack2(WLO, WLO);                                 \
        u64 _wk1 = pack2(WHI, WHI);                                 \
        a[0][CI] = ffma2(m0.x, _wk,  a[0][CI]);                     \
        a[0][CI] = ffma2(m0.y, _wk1, a[0][CI]);                     \
        a[1][CI] = ffma2(m1.x, _wk,  a[1][CI]);                     \
        a[1][CI] = ffma2(m1.y, _wk1, a[1][CI]);                     \
        a[2][CI] = ffma2(m2.x, _wk,  a[2][CI]);                     \
        a[2][CI] = ffma2(m2.y, _wk1, a[2][CI]);                     \
    } while (0)
        COLFMA(wA0.x, wB0.x, 0); COLFMA(wA0.y, wB0.y, 1);
        COLFMA(wA0.z, wB0.z, 2); COLFMA(wA0.w, wB0.w, 3);
        COLFMA(wA1.x, wB1.x, 4); COLFMA(wA1.y, wB1.y, 5);
        COLFMA(wA1.z, wB1.z, 6); COLFMA(wA1.w, wB1.w, 7);
#undef COLFMA
    }
    /* max over this lane's 3 rows, then cross row-group (xor 8), bias, relu */
    u64 m8[8];
#pragma unroll
    for (int c = 0; c < 8; c++)
        m8[c] = max2(max2(a[0][c], a[1][c]), a[2][c]);
#pragma unroll
    for (int c = 0; c < 8; c++)
        m8[c] = max2(m8[c], shfl64x(m8[c], 8));
    const float bc[8] = {bb0.x, bb0.y, bb0.z, bb0.w, bb1.x, bb1.y, bb1.z, bb1.w};
#pragma unroll
    for (int c = 0; c < 8; c++)
        m8[c] = relu2(add2(m8[c], pack2(bc[c], bc[c])));
    /* redistribute to column layout via smem (rg0 -> i0 buf, rg2 -> i1 buf) */
    __syncwarp();
    if ((rg & 1) == 0) {
        u64* buf = mh + ((rg == 0) ? 0 : 6 * MST);
        ulonglong2 s;
        s.x = m8[0]; s.y = m8[1]; *reinterpret_cast<ulonglong2*>(&buf[8 * cg])     = s;
        s.x = m8[2]; s.y = m8[3]; *reinterpret_cast<ulonglong2*>(&buf[8 * cg + 2]) = s;
        s.x = m8[4]; s.y = m8[5]; *reinterpret_cast<ulonglong2*>(&buf[8 * cg + 4]) = s;
        s.x = m8[6]; s.y = m8[7]; *reinterpret_cast<ulonglong2*>(&buf[8 * cg + 6]) = s;
    }
    __syncwarp();
    ulonglong2 r0 = *reinterpret_cast<const ulonglong2*>(&mh[2 * l]);
    u[I0][0] = r0.x; u[I0][1] = r0.y;
    ulonglong2 r1 = *reinterpret_cast<const ulonglong2*>(&mh[6 * MST + 2 * l]);
    u[I0 + 1][0] = r1.x; u[I0 + 1][1] = r1.y;
}

/* === last destination node (i=6), column-style, plain weights === */
__device__ __forceinline__ void edge_one6(u64* __restrict__ mh, const float* __restrict__ wb,
                                          const float* __restrict__ BB, int l,
                                          u64 (&u)[7][2], const u64 (&v)[7][2]) {
    float2 bb = *reinterpret_cast<const float2*>(&BB[2 * l]);
    __syncwarp();
#pragma unroll
    for (int j = 0; j < 6; j++) {
        ulonglong2 mm;
        mm.x = relu2(add2(u[6][0], v[j][0]));
        mm.y = relu2(add2(u[6][1], v[j][1]));
        *reinterpret_cast<ulonglong2*>(&mh[j * MST + 2 * l]) = mm;
    }
    __syncwarp();
    u64 a[6][2];
#pragma unroll
    for (int jj = 0; jj < 6; jj++) { a[jj][0] = 0ULL; a[jj][1] = 0ULL; }
#pragma unroll 1
    for (int k = 0; k < 64; k += 2) {
        float2 w0 = *reinterpret_cast<const float2*>(&wb[k * 64 + 2 * l]);
        float2 w1 = *reinterpret_cast<const float2*>(&wb[(k + 1) * 64 + 2 * l]);
        u64 wx0 = pack2(w0.x, w0.x), wy0 = pack2(w0.y, w0.y);
        u64 wx1 = pack2(w1.x, w1.x), wy1 = pack2(w1.y, w1.y);
#pragma unroll
        for (int jj = 0; jj < 6; jj++) {
            ulonglong2 mv = *reinterpret_cast<const ulonglong2*>(&mh[jj * MST + k]);
            a[jj][0] = ffma2(mv.x, wx0, a[jj][0]);
            a[jj][1] = ffma2(mv.x, wy0, a[jj][1]);
            a[jj][0] = ffma2(mv.y, wx1, a[jj][0]);
            a[jj][1] = ffma2(mv.y, wy1, a[jj][1]);
        }
    }
#pragma unroll
    for (int cc = 0; cc < 2; cc++) {
        float2 m = unpack2(a[0][cc]);
#pragma unroll
        for (int jj = 1; jj < 6; jj++) {
            float2 q = unpack2(a[jj][cc]);
            m.x = fmaxf(m.x, q.x); m.y = fmaxf(m.y, q.y);
        }
        float b = cc ? bb.y : bb.x;
        u[6][cc] = pack2(fmaxf(m.x + b, 0.f), fmaxf(m.y + b, 0.f));
    }
}

__device__ __forceinline__ void edge64(u64* __restrict__ mh, const float* __restrict__ wb,
                                       const float* __restrict__ BB, int l, int rg, int cg,
                                       u64 (&u)[7][2], const u64 (&v)[7][2]) {
    float4 bb0 = *reinterpret_cast<const float4*>(&BB[8 * cg]);
    float4 bb1 = *reinterpret_cast<const float4*>(&BB[8 * cg + 4]);
    edge2d<0>(mh, wb, bb0, bb1, l, rg, cg, u, v);
    edge2d<2>(mh, wb, bb0, bb1, l, rg, cg, u, v);
    edge2d<4>(mh, wb, bb0, bb1, l, rg, cg, u, v);
    edge_one6(mh, wb, BB, l, u, v);
}

/* ================= main fused GNN: one warp per pair of graphs ================= */
__global__ __launch_bounds__(NTHR, 1)
void gnn_main(const float* __restrict__ omega, const float* __restrict__ t,
              const float* __restrict__ wi1, const float* __restrict__ bi1,
              const float* __restrict__ wi2, const float* __restrict__ bi2,
              const float* __restrict__ w1a, const float* __restrict__ b1a,
              const float* __restrict__ w1b, const float* __restrict__ b1b,
              const float* __restrict__ w2a, const float* __restrict__ b2a,
              const float* __restrict__ w2b, const float* __restrict__ b2b,
              const float* __restrict__ w3a, const float* __restrict__ b3a,
              const float* __restrict__ w3b, const float* __restrict__ b3b,
              float* __restrict__ out, int Bn) {
    extern __shared__ float sm[];
    const int tid = threadIdx.x;

    /* ---- weight prologue ---- */
    for (int o = tid; o < 4096; o += NTHR) {
        int k2 = o >> 7, l4 = (o >> 2) & 31, q = o & 3;
        int k = 2 * k2 + (q >> 1), c = 2 * l4 + (q & 1);
        sm[OWI2P + o] = wi2[k * 64 + c];
        sm[OW1B + o] = w1b[o];          /* plain */
        sm[OW2B + o] = w2b[o];          /* plain */
    }
    for (int o = tid; o < 8192; o += NTHR) {
        int k = o >> 7, l4 = (o >> 2) & 31, q = o & 3;
        int c = 2 * l4 + (q & 1);
        float t1 = w1a[k * 64 + c], b1_ = w1a[4096 + k * 64 + c];
        sm[OW1SN + o] = (q < 2) ? (t1 - b1_) : b1_;
        float t2 = w2a[k * 64 + c], b2_ = w2a[6144 + k * 64 + c];
        sm[OW2SN + o] = (q < 2) ? (t2 - b2_) : b2_;
        float t3 = w3a[k * 64 + c], b3_ = w3a[6144 + k * 64 + c];
        sm[OW3SN + o] = (q < 2) ? (t3 - b3_) : b3_;
    }
    for (int i = tid; i < 192; i += NTHR) {
        sm[OWI1 + i] = wi1[i];
        float wv = w3b[i];
        sm[OW3BD + 2 * i]     = wv;
        sm[OW3BD + 2 * i + 1] = wv;
    }
    if (tid < 64) {
        sm[OBI1 + tid] = bi1[tid]; sm[OBI2 + tid] = bi2[tid];
        sm[OB1A + tid] = b1a[tid]; sm[OB1B + tid] = b1b[tid];
        sm[OB2B + tid] = b2b[tid];
    }
    if (tid < 3) sm[OB3B + tid] = b3b[tid];
    __syncthreads();

    const int w = tid >> 5, l = tid & 31;
    const int rg = l >> 3, cg = l & 7;
    u64* const x64 = reinterpret_cast<u64*>(sm + OACT) + w * WARP_ACT;
    u64* const mh  = x64;          /* edge-phase msg buffer (12 padded rows) aliases x */
    u64* const sc  = x64 + 12 * MST;   /* layer-3 reduce scratch (18 u64), 792..810 */

    const float* WI1f = sm + OWI1;

    const int npairs = (Bn + 1) >> 1;
    const int jj3 = l / 3, c3 = l - 3 * jj3;

    u64 u[7][2], v[7][2];

    for (int p = blockIdx.x * NWARP + w; p < npairs; p += gridDim.x * NWARP) {
        const int gA = 2 * p;
        const int gB = (2 * p + 1 < Bn) ? (2 * p + 1) : gA;
        __syncwarp();

        /* per-graph 1/(std+1e-7) */
        const float tA = t[gA], tB = t[gB];
        const float invA = 1.f / (sqrtf((expf(2.f * tA * LN_SIGMA) - 1.f) / (2.f * LN_SIGMA)) + 1e-7f);
        const float invB = 1.f / (sqrtf((expf(2.f * tB * LN_SIGMA) - 1.f) / (2.f * LN_SIGMA)) + 1e-7f);

        /* sigma row indices (tile-quirk: (g*7+n) % B) */
        int ia[7], ib[7];
        {
            int rA = (gA * 7) % Bn, rB = (gB * 7) % Bn;
#pragma unroll
            for (int n = 0; n < 7; n++) {
                int a_ = rA + n; ia[n] = (a_ >= Bn) ? a_ - Bn : a_;
                int b_ = rB + n; ib[n] = (b_ >= Bn) ? b_ - Bn : b_;
            }
        }

        /* ---- init features: hid1 -> x64 scratch; hid2 -> regs -> x64 ---- */
        {
            float2 wd0 = *reinterpret_cast<const float2*>(&WI1f[0 * 64 + 2 * l]);
            float2 wd1 = *reinterpret_cast<const float2*>(&WI1f[1 * 64 + 2 * l]);
            float2 wd2 = *reinterpret_cast<const float2*>(&WI1f[2 * 64 + 2 * l]);
            float2 bb  = *reinterpret_cast<const float2*>(&sm[OBI1 + 2 * l]);
            u64 w0x = pack2(wd0.x, wd0.x), w0y = pack2(wd0.y, wd0.y);
            u64 w1x = pack2(wd1.x, wd1.x), w1y = pack2(wd1.y, wd1.y);
            u64 w2x = pack2(wd2.x, wd2.x), w2y = pack2(wd2.y, wd2.y);
#pragma unroll
            for (int n = 0; n < 7; n++) {
                const float* oA = omega + (size_t)(gA * 7 + n) * 3;
                const float* oB = omega + (size_t)(gB * 7 + n) * 3;
                u64 p0 = pack2(oA[0], oB[0]);
                u64 p1 = pack2(oA[1], oB[1]);
                u64 p2 = pack2(oA[2], oB[2]);
                u64 h0 = pack2(bb.x, bb.x), h1 = pack2(bb.y, bb.y);
                h0 = ffma2(p0, w0x, h0); h0 = ffma2(p1, w1x, h0); h0 = ffma2(p2, w2x, h0);
                h1 = ffma2(p0, w0y, h1); h1 = ffma2(p1, w1y, h1); h1 = ffma2(p2, w2y, h1);
                ulonglong2 hh; hh.x = relu2(h0); hh.y = relu2(h1);
                *reinterpret_cast<ulonglong2*>(&x64[n * 64 + 2 * l]) = hh;
            }
        }
        __syncwarp();
        {
            float2 bi = *reinterpret_cast<const float2*>(&sm[OBI2 + 2 * l]);
#pragma unroll
            for (int n = 0; n < 7; n++) {
                u[n][0] = pack2(bi.x, bi.x); u[n][1] = pack2(bi.y, bi.y);
            }
            const float* wp = sm + OWI2P + 4 * l;
#pragma unroll 1
            for (int k = 0; k < 64; k += 2) {
                float4 wv = *reinterpret_cast<const float4*>(&wp[k * 64]);
                u64 wx0 = pack2(wv.x, wv.x), wy0 = pack2(wv.y, wv.y);
                u64 wx1 = pack2(wv.z, wv.z), wy1 = pack2(wv.w, wv.w);
#pragma unroll
                for (int n = 0; n < 7; n++) {
                    ulonglong2 hv = *reinterpret_cast<const ulonglong2*>(&x64[n * 64 + k]);
                    u[n][0] = ffma2(hv.x, wx0, u[n][0]);
                    u[n][1] = ffma2(hv.x, wy0, u[n][1]);
                    u[n][0] = ffma2(hv.y, wx1, u[n][0]);
                    u[n][1] = ffma2(hv.y, wy1, u[n][1]);
                }
            }
        }
        __syncwarp();
#pragma unroll
        for (int n = 0; n < 7; n++) {
            ulonglong2 xx; xx.x = u[n][0]; xx.y = u[n][1];
            *reinterpret_cast<ulonglong2*>(&x64[n * 64 + 2 * l]) = xx;
        }
        __syncwarp();

        /* ---- layer 1: init u=bias, v=0 ---- */
        {
            float2 ba = *reinterpret_cast<const float2*>(&sm[OB1A + 2 * l]);
#pragma unroll
            for (int n = 0; n < 7; n++) {
                u[n][0] = pack2(ba.x, ba.x); u[n][1] = pack2(ba.y, ba.y);
                v[n][0] = 0ULL;              v[n][1] = 0ULL;
            }
        }
        uv64(x64, sm + OW1SN, l, u, v);
        edge64(mh, sm + OW1B, sm + OB1B, l, rg, cg, u, v);
        __syncwarp();
#pragma unroll
        for (int n = 0; n < 7; n++) {
            ulonglong2 xx; xx.x = u[n][0]; xx.y = u[n][1];
            *reinterpret_cast<ulonglong2*>(&x64[n * 64 + 2 * l]) = xx;
        }
        __syncwarp();

        /* ---- layer 2: init u,v from precomputed sigma contributions ---- */
#pragma unroll
        for (int n = 0; n < 7; n++) {
            const float* yA = g_Y + (size_t)ia[n] * 256;
            const float* yB = g_Y + (size_t)ib[n] * 256;
            float2 sA = *reinterpret_cast<const float2*>(&yA[2 * l]);
            float2 sB = *reinterpret_cast<const float2*>(&yB[2 * l]);
            float2 nA = *reinterpret_cast<const float2*>(&yA[64 + 2 * l]);
            float2 nB = *reinterpret_cast<const float2*>(&yB[64 + 2 * l]);
            u[n][0] = pack2(sA.x, sB.x); u[n][1] = pack2(sA.y, sB.y);
            v[n][0] = pack2(nA.x, nB.x); v[n][1] = pack2(nA.y, nB.y);
        }
        uv64(x64, sm + OW2SN, l, u, v);
        edge64(mh, sm + OW2B, sm + OB2B, l, rg, cg, u, v);
        __syncwarp();
#pragma unroll
        for (int n = 0; n < 7; n++) {
            ulonglong2 xx; xx.x = u[n][0]; xx.y = u[n][1];
            *reinterpret_cast<ulonglong2*>(&x64[n * 64 + 2 * l]) = xx;
        }
        __syncwarp();

        /* ---- layer 3: init from Y, uv, 3-wide edge output ---- */
#pragma unroll
        for (int n = 0; n < 7; n++) {
            const float* yA = g_Y + (size_t)ia[n] * 256;
            const float* yB = g_Y + (size_t)ib[n] * 256;
            float2 sA = *reinterpret_cast<const float2*>(&yA[128 + 2 * l]);
            float2 sB = *reinterpret_cast<const float2*>(&yB[128 + 2 * l]);
            float2 nA = *reinterpret_cast<const float2*>(&yA[192 + 2 * l]);
            float2 nB = *reinterpret_cast<const float2*>(&yB[192 + 2 * l]);
            u[n][0] = pack2(sA.x, sB.x); u[n][1] = pack2(sA.y, sB.y);
            v[n][0] = pack2(nA.x, nB.x); v[n][1] = pack2(nA.y, nB.y);
        }
        uv64(x64, sm + OW3SN, l, u, v);
#pragma unroll
        for (int i = 0; i < 7; i++) {
            __syncwarp();
#pragma unroll
            for (int j = 0; j < 7; j++) {
                if (j == i) continue;
                const int jj = (j < i) ? j : j - 1;
                ulonglong2 mm;
                mm.x = relu2(add2(u[i][0], v[j][0]));
                mm.y = relu2(add2(u[i][1], v[j][1]));
                *reinterpret_cast<ulonglong2*>(&mh[jj * MST + 2 * l]) = mm;
            }
            __syncwarp();
            if (l < 18) {
                u64 acc = 0ULL;
                const float* wdp = sm + OW3BD;
#pragma unroll 1
                for (int k = 0; k < 64; k += 2) {
                    ulonglong2 mv = *reinterpret_cast<const ulonglong2*>(&mh[jj3 * MST + k]);
                    u64 wd0 = *reinterpret_cast<const u64*>(&wdp[2 * (k * 3 + c3)]);
                    u64 wd1 = *reinterpret_cast<const u64*>(&wdp[2 * ((k + 1) * 3 + c3)]);
                    acc = ffma2(mv.x, wd0, acc);
                    acc = ffma2(mv.y, wd1, acc);
                }
                sc[l] = acc;
            }
            __syncwarp();
            if (l < 3) {
                float2 m = unpack2(sc[l]);
#pragma unroll
                for (int jq = 1; jq < 6; jq++) {
                    float2 q = unpack2(sc[jq * 3 + l]);
                    m.x = fmaxf(m.x, q.x); m.y = fmaxf(m.y, q.y);
                }
                float b3 = sm[OB3B + l];
                out[(size_t)(gA * 7 + i) * 3 + l] = (m.x + b3) * invA;
                out[(size_t)(gB * 7 + i) * 3 + l] = (m.y + b3) * invB;
            }
        }
    }
}

extern "C" void kernel_launch(void* const* d_in, const int* in_sizes, int n_in,
                              void* d_out, int out_size) {
    const float* omega = (const float*)d_in[0];
    /* d_in[1] edge_index (fixed all-pairs; computed implicitly), d_in[3] num_objs unused */
    const float* t   = (const float*)d_in[2];
    const float* Wf  = (const float*)d_in[4];
    const float* wi1 = (const float*)d_in[5];  const float* bi1 = (const float*)d_in[6];
    const float* wi2 = (const float*)d_in[7];  const float* bi2 = (const float*)d_in[8];
    const float* wt  = (const float*)d_in[9];  const float* bt  = (const float*)d_in[10];
    const float* w1a = (const float*)d_in[11]; const float* b1a = (const float*)d_in[12];
    const float* w1b = (const float*)d_in[13]; const float* b1b = (const float*)d_in[14];
    const float* w2a = (const float*)d_in[15]; const float* b2a = (const float*)d_in[16];
    const float* w2b = (const float*)d_in[17]; const float* b2b = (const float*)d_in[18];
    const float* w3a = (const float*)d_in[19]; const float* b3a = (const float*)d_in[20];
    const float* w3b = (const float*)d_in[21]; const float* b3b = (const float*)d_in[22];
    float* out = (float*)d_out;

    int Bn = in_sizes[2];
    if (Bn > MAXB) Bn = MAXB;

    prep_kernel<<<(Bn + 255) / 256, 256>>>(t, Wf, wt, bt, w2a, b2a, w3a, b3a, Bn);

    cudaFuncSetAttribute(gnn_main, cudaFuncAttributeMaxDynamicSharedMemorySize, SMEM_BYTES);
    int dev = 0, nsm = 148;
    cudaGetDevice(&dev);
    cudaDeviceGetAttribute(&nsm, cudaDevAttrMultiProcessorCount, dev);

    gnn_main<<<nsm, NTHR, SMEM_BYTES>>>(omega, t, wi1, bi1, wi2, bi2,
                                        w1a, b1a, w1b, b1b,
                                        w2a, b2a, w2b, b2b,
                                        w3a, b3a, w3b, b3b, out, Bn);
}